// round 2
// baseline (speedup 1.0000x reference)
#include <cuda_runtime.h>
#include <cuda_bf16.h>

// Problem constants (from reference)
#define N_POINTS  1048576
#define DD        64                 // hash grid per dim
#define NUM_BINS  (DD*DD*DD)         // 262144
#define LL        128                // dense lattice side
#define TT        8                  // atom types
#define CAP       8                  // buffer slots per bin
#define STORE_CAP 32                 // scratch index capacity per bin (P(overflow) ~ 1e-18)

#define LAT_ELEMS  (LL*LL*LL*TT)     // 16777216
#define BUF_ELEMS  (NUM_BINS*CAP*3)  // 6291456

// Scratch: per-bin counters + per-bin index lists (static __device__ = allowed)
__device__ int g_count[NUM_BINS];
__device__ int g_idx[NUM_BINS * STORE_CAP];

// ---------------------------------------------------------------------------
// Pass 1: per-point binning (histogram + index scatter) fused with the
// Gaussian splat into the dense lattice.
// ---------------------------------------------------------------------------
__global__ void __launch_bounds__(256)
bin_splat_kernel(const float* __restrict__ pts,
                 const int* __restrict__ mask,        // bool passed as int32
                 const int* __restrict__ types,
                 float* __restrict__ lat)
{
    int i = blockIdx.x * blockDim.x + threadIdx.x;
    if (i >= N_POINTS) return;
    if (!mask[i]) return;  // masked points contribute nothing anywhere

    float px = pts[3*i + 0];
    float py = pts[3*i + 1];
    float pz = pts[3*i + 2];

    // ---- spatial hash (D=64): cell = clip(floor(p/BOX*D), 0, 63); p*2 == p/32*64 exactly
    int bx = min(max((int)floorf(px * 2.0f), 0), DD - 1);
    int by = min(max((int)floorf(py * 2.0f), 0), DD - 1);
    int bz = min(max((int)floorf(pz * 2.0f), 0), DD - 1);
    int bin = (bx * DD + by) * DD + bz;
    int pos = atomicAdd(&g_count[bin], 1);
    if (pos < STORE_CAP) g_idx[bin * STORE_CAP + pos] = i;

    // ---- Gaussian splat (L=128): cell = floor(p/BOX*L); p*4 == p/32*128 exactly
    int t  = types[i];
    int cx = (int)floorf(px * 4.0f);
    int cy = (int)floorf(py * 4.0f);
    int cz = (int)floorf(pz * 4.0f);

    // separable per-axis Gaussian factors: exp(-d2/(2*gw^2)), gw=0.3
    const float inv = 1.0f / (2.0f * 0.3f * 0.3f);   // 5.5555553
    float ex[3], ey[3], ez[3];
    #pragma unroll
    for (int o = 0; o < 3; o++) {
        float vx = px - ((float)(cx + o - 1) + 0.5f) * 0.25f;
        float vy = py - ((float)(cy + o - 1) + 0.5f) * 0.25f;
        float vz = pz - ((float)(cz + o - 1) + 0.5f) * 0.25f;
        ex[o] = __expf(-vx * vx * inv);
        ey[o] = __expf(-vy * vy * inv);
        ez[o] = __expf(-vz * vz * inv);
    }

    #pragma unroll
    for (int ix = 0; ix < 3; ix++) {
        int x = cx + ix - 1;
        if ((unsigned)x >= (unsigned)LL) continue;
        #pragma unroll
        for (int iy = 0; iy < 3; iy++) {
            int y = cy + iy - 1;
            if ((unsigned)y >= (unsigned)LL) continue;
            float exy = ex[ix] * ey[iy];
            int base_xy = (x * LL + y) * LL;
            #pragma unroll
            for (int iz = 0; iz < 3; iz++) {
                int z = cz + iz - 1;
                if ((unsigned)z >= (unsigned)LL) continue;
                float w = exy * ez[iz];
                atomicAdd(&lat[(base_xy + z) * TT + t], w);
            }
        }
    }
}

// ---------------------------------------------------------------------------
// Pass 2: per-bin stable ordering.  Sort stored original indices ascending
// (reproduces jnp stable-argsort slot assignment), write first CAP points.
// ---------------------------------------------------------------------------
__global__ void __launch_bounds__(256)
fill_buffer_kernel(const float* __restrict__ pts,
                   float* __restrict__ buf,
                   float* __restrict__ bmask)
{
    int b = blockIdx.x * blockDim.x + threadIdx.x;
    if (b >= NUM_BINS) return;

    int cnt = g_count[b];
    int m = min(cnt, STORE_CAP);

    int idx[STORE_CAP];
    for (int k = 0; k < m; k++) idx[k] = g_idx[b * STORE_CAP + k];

    // insertion sort (avg m ~= 4) -> ascending original index == stable argsort order
    for (int k = 1; k < m; k++) {
        int v = idx[k];
        int j = k - 1;
        while (j >= 0 && idx[j] > v) { idx[j + 1] = idx[j]; j--; }
        idx[j + 1] = v;
    }

    int nval = min(cnt, CAP);
    #pragma unroll
    for (int s = 0; s < CAP; s++) {
        float x = 0.f, y = 0.f, z = 0.f, mv = 0.f;
        if (s < nval) {
            int i = idx[s];
            x = pts[3*i + 0];
            y = pts[3*i + 1];
            z = pts[3*i + 2];
            mv = 1.0f;
        }
        long long o = ((long long)b * CAP + s) * 3;
        buf[o + 0] = x;
        buf[o + 1] = y;
        buf[o + 2] = z;
        bmask[b * CAP + s] = mv;
    }
}

// ---------------------------------------------------------------------------
extern "C" void kernel_launch(void* const* d_in, const int* in_sizes, int n_in,
                              void* d_out, int out_size)
{
    const float* points = (const float*)d_in[0];
    const int*   mask   = (const int*)d_in[1];
    const int*   types  = (const int*)d_in[2];

    float* out   = (float*)d_out;
    float* lat   = out;                       // [128,128,128,8]
    float* buf   = out + LAT_ELEMS;           // [262144,8,3]
    float* bmask = buf + BUF_ELEMS;           // [262144,8]

    // zero lattice (accumulated via atomics) and bin counters
    cudaMemsetAsync(lat, 0, (size_t)LAT_ELEMS * sizeof(float), 0);
    void* cptr = nullptr;
    cudaGetSymbolAddress(&cptr, g_count);
    cudaMemsetAsync(cptr, 0, (size_t)NUM_BINS * sizeof(int), 0);

    bin_splat_kernel<<<(N_POINTS + 255) / 256, 256>>>(points, mask, types, lat);
    fill_buffer_kernel<<<(NUM_BINS + 255) / 256, 256>>>(points, buf, bmask);
}

// round 3
// speedup vs baseline: 1.1336x; 1.1336x over previous
#include <cuda_runtime.h>
#include <cuda_bf16.h>

// Problem constants (from reference)
#define N_POINTS  1048576
#define DD        64                 // hash grid per dim
#define NUM_BINS  (DD*DD*DD)         // 262144
#define LL        128                // dense lattice side
#define TT        8                  // atom types
#define CAP       8                  // buffer slots per bin
#define STORE_CAP 32                 // scratch capacity per bin (P(overflow) ~ 1e-24)

#define LAT_ELEMS  (LL*LL*LL*TT)     // 16777216
#define BUF_ELEMS  (NUM_BINS*CAP*3)  // 6291456

// Scratch: per-bin counters + per-bin (x,y,z,idx) records (static __device__ = allowed)
__device__ int    g_count[NUM_BINS];
__device__ float4 g_pts[NUM_BINS * STORE_CAP];   // 134 MB

// ---------------------------------------------------------------------------
// Pass 1: binning (record scatter) fused with Gaussian splat.
// Interior fast path: all 27 lattice targets are base + compile-time immediate.
// ---------------------------------------------------------------------------
__global__ void __launch_bounds__(256)
bin_splat_kernel(const float* __restrict__ pts,
                 const int* __restrict__ mask,        // bool passed as int32
                 const int* __restrict__ types,
                 float* __restrict__ lat)
{
    int i = blockIdx.x * blockDim.x + threadIdx.x;
    if (i >= N_POINTS) return;
    if (!mask[i]) return;

    float px = pts[3*i + 0];
    float py = pts[3*i + 1];
    float pz = pts[3*i + 2];

    // ---- spatial hash (D=64): p*2 == p/BOX*D exactly
    int bx = min(max((int)floorf(px * 2.0f), 0), DD - 1);
    int by = min(max((int)floorf(py * 2.0f), 0), DD - 1);
    int bz = min(max((int)floorf(pz * 2.0f), 0), DD - 1);
    int bin = (bx * DD + by) * DD + bz;
    int pos = atomicAdd(&g_count[bin], 1);
    if (pos < STORE_CAP)
        g_pts[bin * STORE_CAP + pos] = make_float4(px, py, pz, __int_as_float(i));

    // ---- Gaussian splat (L=128): p*4 == p/BOX*L exactly
    int t  = types[i];
    int cx = (int)floorf(px * 4.0f);
    int cy = (int)floorf(py * 4.0f);
    int cz = (int)floorf(pz * 4.0f);

    const float inv = 1.0f / (2.0f * 0.3f * 0.3f);
    float ex[3], ey[3], ez[3];
    #pragma unroll
    for (int o = 0; o < 3; o++) {
        float vx = px - ((float)(cx + o - 1) + 0.5f) * 0.25f;
        float vy = py - ((float)(cy + o - 1) + 0.5f) * 0.25f;
        float vz = pz - ((float)(cz + o - 1) + 0.5f) * 0.25f;
        ex[o] = __expf(-vx * vx * inv);
        ey[o] = __expf(-vy * vy * inv);
        ez[o] = __expf(-vz * vz * inv);
    }

    float* base = lat + ((size_t)((cx * LL + cy) * LL + cz)) * TT + t;

    bool interior = ((unsigned)(cx - 1) < (unsigned)(LL - 2)) &&
                    ((unsigned)(cy - 1) < (unsigned)(LL - 2)) &&
                    ((unsigned)(cz - 1) < (unsigned)(LL - 2));

    if (interior) {
        // all offsets compile-time: RED [Rbase + imm]
        #pragma unroll
        for (int ix = 0; ix < 3; ix++) {
            #pragma unroll
            for (int iy = 0; iy < 3; iy++) {
                float exy = ex[ix] * ey[iy];
                float* p = base + ((ix - 1) * LL + (iy - 1)) * (LL * TT);
                atomicAdd(p - TT, exy * ez[0]);
                atomicAdd(p,      exy * ez[1]);
                atomicAdd(p + TT, exy * ez[2]);
            }
        }
    } else {
        #pragma unroll
        for (int ix = 0; ix < 3; ix++) {
            int x = cx + ix - 1;
            if ((unsigned)x >= (unsigned)LL) continue;
            #pragma unroll
            for (int iy = 0; iy < 3; iy++) {
                int y = cy + iy - 1;
                if ((unsigned)y >= (unsigned)LL) continue;
                float exy = ex[ix] * ey[iy];
                int base_xy = (x * LL + y) * LL;
                #pragma unroll
                for (int iz = 0; iz < 3; iz++) {
                    int z = cz + iz - 1;
                    if ((unsigned)z >= (unsigned)LL) continue;
                    atomicAdd(&lat[(size_t)(base_xy + z) * TT + t], exy * ez[iz]);
                }
            }
        }
    }
}

// ---------------------------------------------------------------------------
// Pass 2: per-bin stable ordering from scratch records (no random gather).
// Register-resident top-8 selection network keyed by (orig_index<<5 | pos).
// ---------------------------------------------------------------------------
__global__ void __launch_bounds__(256)
fill_buffer_kernel(float* __restrict__ buf,
                   float* __restrict__ bmask)
{
    int b = blockIdx.x * blockDim.x + threadIdx.x;
    if (b >= NUM_BINS) return;

    int cnt = g_count[b];
    int m = min(cnt, STORE_CAP);

    int key[CAP];
    #pragma unroll
    for (int s = 0; s < CAP; s++) key[s] = 0x7FFFFFFF;

    const float4* rec = &g_pts[b * STORE_CAP];
    for (int e = 0; e < m; e++) {
        int k = (__float_as_int(rec[e].w) << 5) | e;   // idx<2^20 -> no overflow
        #pragma unroll
        for (int j = 0; j < CAP; j++) {
            int lo = min(k, key[j]);
            int hi = max(k, key[j]);
            key[j] = lo;
            k = hi;
        }
    }

    int nval = min(cnt, CAP);
    float o[CAP * 3];
    float mk[CAP];
    #pragma unroll
    for (int s = 0; s < CAP; s++) {
        float x = 0.f, y = 0.f, z = 0.f, mv = 0.f;
        if (s < nval) {
            float4 r = rec[key[s] & (STORE_CAP - 1)];  // L1 hit (just touched)
            x = r.x; y = r.y; z = r.z; mv = 1.0f;
        }
        o[3*s + 0] = x; o[3*s + 1] = y; o[3*s + 2] = z;
        mk[s] = mv;
    }

    // vectorized output: 96 B coords + 32 B mask per bin, 16B-aligned
    float4* bp = (float4*)(buf + (size_t)b * (CAP * 3));
    #pragma unroll
    for (int q = 0; q < 6; q++)
        bp[q] = make_float4(o[4*q + 0], o[4*q + 1], o[4*q + 2], o[4*q + 3]);

    float4* mp = (float4*)(bmask + (size_t)b * CAP);
    mp[0] = make_float4(mk[0], mk[1], mk[2], mk[3]);
    mp[1] = make_float4(mk[4], mk[5], mk[6], mk[7]);
}

// ---------------------------------------------------------------------------
extern "C" void kernel_launch(void* const* d_in, const int* in_sizes, int n_in,
                              void* d_out, int out_size)
{
    const float* points = (const float*)d_in[0];
    const int*   mask   = (const int*)d_in[1];
    const int*   types  = (const int*)d_in[2];

    float* out   = (float*)d_out;
    float* lat   = out;                       // [128,128,128,8]
    float* buf   = out + LAT_ELEMS;           // [262144,8,3]
    float* bmask = buf + BUF_ELEMS;           // [262144,8]

    cudaMemsetAsync(lat, 0, (size_t)LAT_ELEMS * sizeof(float), 0);
    void* cptr = nullptr;
    cudaGetSymbolAddress(&cptr, g_count);
    cudaMemsetAsync(cptr, 0, (size_t)NUM_BINS * sizeof(int), 0);

    bin_splat_kernel<<<(N_POINTS + 255) / 256, 256>>>(points, mask, types, lat);
    fill_buffer_kernel<<<(NUM_BINS + 255) / 256, 256>>>(buf, bmask);
}

// round 4
// speedup vs baseline: 1.3882x; 1.2246x over previous
#include <cuda_runtime.h>
#include <cuda_bf16.h>

#define N_POINTS  1048576
#define DD        64
#define NUM_BINS  (DD*DD*DD)         // 262144
#define LL        128
#define TT        8
#define CAP       8
#define STORE_CAP 32

#define LAT_ELEMS  (LL*LL*LL*TT)     // 16777216
#define BUF_ELEMS  (NUM_BINS*CAP*3)

__device__ int    g_count[NUM_BINS];
__device__ float4 g_pts[NUM_BINS * STORE_CAP];   // (x,y,z, (idx<<3)|type)

// ---------------------------------------------------------------------------
// Gaussian splat of one point (used by pass 2, and pass-1 overflow fallback)
// ---------------------------------------------------------------------------
__device__ __forceinline__ void splat_point(float px, float py, float pz, int t,
                                            float* __restrict__ lat)
{
    int cx = (int)floorf(px * 4.0f);
    int cy = (int)floorf(py * 4.0f);
    int cz = (int)floorf(pz * 4.0f);

    const float inv = 1.0f / (2.0f * 0.3f * 0.3f);
    float ex[3], ey[3], ez[3];
    #pragma unroll
    for (int o = 0; o < 3; o++) {
        float vx = px - ((float)(cx + o - 1) + 0.5f) * 0.25f;
        float vy = py - ((float)(cy + o - 1) + 0.5f) * 0.25f;
        float vz = pz - ((float)(cz + o - 1) + 0.5f) * 0.25f;
        ex[o] = __expf(-vx * vx * inv);
        ey[o] = __expf(-vy * vy * inv);
        ez[o] = __expf(-vz * vz * inv);
    }

    float* base = lat + ((size_t)((cx * LL + cy) * LL + cz)) * TT + t;

    bool interior = ((unsigned)(cx - 1) < (unsigned)(LL - 2)) &&
                    ((unsigned)(cy - 1) < (unsigned)(LL - 2)) &&
                    ((unsigned)(cz - 1) < (unsigned)(LL - 2));

    if (interior) {
        #pragma unroll
        for (int ix = 0; ix < 3; ix++) {
            #pragma unroll
            for (int iy = 0; iy < 3; iy++) {
                float exy = ex[ix] * ey[iy];
                float* p = base + ((ix - 1) * LL + (iy - 1)) * (LL * TT);
                atomicAdd(p - TT, exy * ez[0]);
                atomicAdd(p,      exy * ez[1]);
                atomicAdd(p + TT, exy * ez[2]);
            }
        }
    } else {
        #pragma unroll
        for (int ix = 0; ix < 3; ix++) {
            int x = cx + ix - 1;
            if ((unsigned)x >= (unsigned)LL) continue;
            #pragma unroll
            for (int iy = 0; iy < 3; iy++) {
                int y = cy + iy - 1;
                if ((unsigned)y >= (unsigned)LL) continue;
                float exy = ex[ix] * ey[iy];
                int base_xy = (x * LL + y) * LL;
                #pragma unroll
                for (int iz = 0; iz < 3; iz++) {
                    int z = cz + iz - 1;
                    if ((unsigned)z >= (unsigned)LL) continue;
                    atomicAdd(&lat[(size_t)(base_xy + z) * TT + t], exy * ez[iz]);
                }
            }
        }
    }
}

// ---------------------------------------------------------------------------
// Pass 1: bin scatter only. Record carries coords + (idx<<3 | type).
// ---------------------------------------------------------------------------
__global__ void __launch_bounds__(256)
bin_kernel(const float* __restrict__ pts,
           const int* __restrict__ mask,
           const int* __restrict__ types,
           float* __restrict__ lat)
{
    int i = blockIdx.x * blockDim.x + threadIdx.x;
    if (i >= N_POINTS) return;
    if (!mask[i]) return;

    float px = pts[3*i + 0];
    float py = pts[3*i + 1];
    float pz = pts[3*i + 2];
    int   t  = types[i];

    int bx = min(max((int)floorf(px * 2.0f), 0), DD - 1);
    int by = min(max((int)floorf(py * 2.0f), 0), DD - 1);
    int bz = min(max((int)floorf(pz * 2.0f), 0), DD - 1);
    int bin = (bx * DD + by) * DD + bz;
    int pos = atomicAdd(&g_count[bin], 1);
    if (pos < STORE_CAP) {
        g_pts[bin * STORE_CAP + pos] =
            make_float4(px, py, pz, __int_as_float((i << 3) | t));
    } else {
        // overflow (P ~ 1e-24): splat now so nothing is lost
        splat_point(px, py, pz, t, lat);
    }
}

// ---------------------------------------------------------------------------
// Pass 2: splat from binned records. tid -> (bin = tid/8, slot = tid%8, +8..)
// Warp lanes cover 4 consecutive z-bins -> RED addresses share cache lines.
// ---------------------------------------------------------------------------
__global__ void __launch_bounds__(256)
splat_kernel(float* __restrict__ lat)
{
    int tid = blockIdx.x * blockDim.x + threadIdx.x;   // NUM_BINS*8 threads
    int bin  = tid >> 3;
    int slot = tid & 7;
    if (bin >= NUM_BINS) return;

    int m = min(g_count[bin], STORE_CAP);
    for (int s = slot; s < m; s += 8) {
        float4 r = g_pts[bin * STORE_CAP + s];
        int packed = __float_as_int(r.w);
        splat_point(r.x, r.y, r.z, packed & 7, lat);
    }
}

// ---------------------------------------------------------------------------
// Pass 3: per-bin stable ordering -> buffer + mask.
// ---------------------------------------------------------------------------
__global__ void __launch_bounds__(256)
fill_buffer_kernel(float* __restrict__ buf,
                   float* __restrict__ bmask)
{
    int b = blockIdx.x * blockDim.x + threadIdx.x;
    if (b >= NUM_BINS) return;

    int cnt = g_count[b];
    int m = min(cnt, STORE_CAP);

    int key[CAP];
    #pragma unroll
    for (int s = 0; s < CAP; s++) key[s] = 0x7FFFFFFF;

    const float4* rec = &g_pts[(size_t)b * STORE_CAP];
    for (int e = 0; e < m; e++) {
        // packed=(i<<3)|t  ->  key=(i<<8)|(t<<5)|e : sorts by original index i
        int k = (__float_as_int(rec[e].w) << 5) | e;
        #pragma unroll
        for (int j = 0; j < CAP; j++) {
            int lo = min(k, key[j]);
            int hi = max(k, key[j]);
            key[j] = lo;
            k = hi;
        }
    }

    int nval = min(cnt, CAP);
    float o[CAP * 3];
    float mk[CAP];
    #pragma unroll
    for (int s = 0; s < CAP; s++) {
        float x = 0.f, y = 0.f, z = 0.f, mv = 0.f;
        if (s < nval) {
            float4 r = rec[key[s] & (STORE_CAP - 1)];
            x = r.x; y = r.y; z = r.z; mv = 1.0f;
        }
        o[3*s + 0] = x; o[3*s + 1] = y; o[3*s + 2] = z;
        mk[s] = mv;
    }

    float4* bp = (float4*)(buf + (size_t)b * (CAP * 3));
    #pragma unroll
    for (int q = 0; q < 6; q++)
        bp[q] = make_float4(o[4*q + 0], o[4*q + 1], o[4*q + 2], o[4*q + 3]);

    float4* mp = (float4*)(bmask + (size_t)b * CAP);
    mp[0] = make_float4(mk[0], mk[1], mk[2], mk[3]);
    mp[1] = make_float4(mk[4], mk[5], mk[6], mk[7]);
}

// ---------------------------------------------------------------------------
extern "C" void kernel_launch(void* const* d_in, const int* in_sizes, int n_in,
                              void* d_out, int out_size)
{
    const float* points = (const float*)d_in[0];
    const int*   mask   = (const int*)d_in[1];
    const int*   types  = (const int*)d_in[2];

    float* out   = (float*)d_out;
    float* lat   = out;                       // [128,128,128,8]
    float* buf   = out + LAT_ELEMS;           // [262144,8,3]
    float* bmask = buf + BUF_ELEMS;           // [262144,8]

    cudaMemsetAsync(lat, 0, (size_t)LAT_ELEMS * sizeof(float), 0);
    void* cptr = nullptr;
    cudaGetSymbolAddress(&cptr, g_count);
    cudaMemsetAsync(cptr, 0, (size_t)NUM_BINS * sizeof(int), 0);

    bin_kernel<<<(N_POINTS + 255) / 256, 256>>>(points, mask, types, lat);
    splat_kernel<<<(NUM_BINS * 8 + 255) / 256, 256>>>(lat);
    fill_buffer_kernel<<<(NUM_BINS + 255) / 256, 256>>>(buf, bmask);
}